// round 1
// baseline (speedup 1.0000x reference)
#include <cuda_runtime.h>
#include <cstdint>

#define NTAGS 24
#define SEQ   512
#define BATCH 2048
#define WARPS_PER_BLOCK 4
#define THREADS (WARPS_PER_BLOCK * 32)

// Per-batch partial results (log_den - log_num). Deterministic two-pass reduce.
__device__ float g_part[BATCH];

__global__ void __launch_bounds__(THREADS) crf_fwd_kernel(
    const float* __restrict__ emissions,   // [BATCH, SEQ, NTAGS]
    const int*   __restrict__ tags,        // [BATCH, SEQ]
    const int*   __restrict__ mask,        // [BATCH, SEQ]
    const float* __restrict__ trans)       // [NTAGS, NTAGS]
{
    __shared__ float s_traw[NTAGS * NTAGS];
    __shared__ __align__(16) float s_p[WARPS_PER_BLOCK][2][32];

    const int tid  = threadIdx.x;
    const int lane = tid & 31;
    const int wid  = tid >> 5;
    const int b    = blockIdx.x * WARPS_PER_BLOCK + wid;

    // Raw transitions in SMEM for gold-score lookups.
    for (int i = tid; i < NTAGS * NTAGS; i += THREADS) s_traw[i] = trans[i];
    __syncthreads();

    const bool act = (lane < NTAGS);

    // tcol[i] = exp(trans[i][lane])  — column of expT owned by this lane.
    float tcol[NTAGS];
#pragma unroll
    for (int i = 0; i < NTAGS; i++)
        tcol[i] = act ? __expf(trans[i * NTAGS + lane]) : 0.0f;

    const float* em = emissions + (size_t)b * (SEQ * NTAGS);
    const int*   tg = tags + (size_t)b * SEQ;
    const int*   mk = mask + (size_t)b * SEQ;

    // ---- t = 0: alpha0 = emissions[:,0] ----
    float e0 = act ? em[lane] : -1e30f;
    float m0 = e0;
#pragma unroll
    for (int o = 16; o; o >>= 1)
        m0 = fmaxf(m0, __shfl_xor_sync(0xffffffffu, m0, o));
    float p = act ? __expf(e0 - m0) : 0.0f;   // p[j] = exp(alpha[j] - C)
    float C = m0;                              // running log-scale

    const int   tag0 = tg[0];
    const int   mk0  = mk[0];
    float gold = mk0 ? __shfl_sync(0xffffffffu, e0, tag0) : 0.0f;
    int   prev_tag = tag0;

    // Prefetch t = 1
    float e_nx   = act ? em[NTAGS + lane] : -1e30f;
    int   tag_nx = tg[1];
    int   mk_nx  = mk[1];

    float* pw = &s_p[wid][0][0];

#pragma unroll 4
    for (int t = 1; t < SEQ; t++) {
        const float e   = e_nx;
        const int   tag = tag_nx;
        const int   m_t = mk_nx;

        const int tn = (t + 1 < SEQ) ? (t + 1) : (SEQ - 1);
        e_nx   = act ? em[tn * NTAGS + lane] : -1e30f;
        tag_nx = tg[tn];
        mk_nx  = mk[tn];

        // Publish p to this warp's double-buffered SMEM slot.
        float* buf = pw + ((t & 1) << 5);
        buf[lane] = p;
        __syncwarp();

        // s[lane] = sum_i p[i] * expT[i][lane]  (broadcast LDS.128 reads)
        const float4* b4 = (const float4*)buf;
        const float4 P0 = b4[0], P1 = b4[1], P2 = b4[2],
                     P3 = b4[3], P4 = b4[4], P5 = b4[5];
        float s0 = P0.x * tcol[0];
        float s1 = P0.y * tcol[1];
        float s2 = P0.z * tcol[2];
        float s3 = P0.w * tcol[3];
        s0 = fmaf(P1.x, tcol[4],  s0);
        s1 = fmaf(P1.y, tcol[5],  s1);
        s2 = fmaf(P1.z, tcol[6],  s2);
        s3 = fmaf(P1.w, tcol[7],  s3);
        s0 = fmaf(P2.x, tcol[8],  s0);
        s1 = fmaf(P2.y, tcol[9],  s1);
        s2 = fmaf(P2.z, tcol[10], s2);
        s3 = fmaf(P2.w, tcol[11], s3);
        s0 = fmaf(P3.x, tcol[12], s0);
        s1 = fmaf(P3.y, tcol[13], s1);
        s2 = fmaf(P3.z, tcol[14], s2);
        s3 = fmaf(P3.w, tcol[15], s3);
        s0 = fmaf(P4.x, tcol[16], s0);
        s1 = fmaf(P4.y, tcol[17], s1);
        s2 = fmaf(P4.z, tcol[18], s2);
        s3 = fmaf(P4.w, tcol[19], s3);
        s0 = fmaf(P5.x, tcol[20], s0);
        s1 = fmaf(P5.y, tcol[21], s1);
        s2 = fmaf(P5.z, tcol[22], s2);
        s3 = fmaf(P5.w, tcol[23], s3);
        const float s = (s0 + s1) + (s2 + s3);

        // alpha_t[j] = log s[j] + emit[j] + C  (kept linear: u = s * exp(e))
        const float u = s * __expf(e);
        p = m_t ? u : p;

        // Gold score: emissions[b,t,tag] + trans[prev_tag, tag], masked.
        const float ee = __shfl_sync(0xffffffffu, e, tag);
        if (m_t) gold += ee + s_traw[prev_tag * NTAGS + tag];
        prev_tag = tag;

        // Rescale every 4 steps (worst-case growth e^13/step, fp32 max e^88).
        if ((t & 3) == 0) {
            float m = p;
#pragma unroll
            for (int o = 16; o; o >>= 1)
                m = fmaxf(m, __shfl_xor_sync(0xffffffffu, m, o));
            const float r = 1.0f / m;
            p *= r;
            C += __logf(m);
        }
    }

    // log_den = C + log(sum_j p[j])  (final max-rescaled logsumexp)
    float m = p;
#pragma unroll
    for (int o = 16; o; o >>= 1)
        m = fmaxf(m, __shfl_xor_sync(0xffffffffu, m, o));
    float z = p * (1.0f / m);
    float zs = z;
#pragma unroll
    for (int o = 16; o; o >>= 1)
        zs += __shfl_xor_sync(0xffffffffu, zs, o);
    const float log_den = C + __logf(m) + __logf(zs);

    if (lane == 0) g_part[b] = log_den - gold;
}

__global__ void crf_reduce_kernel(float* __restrict__ out)
{
    __shared__ float sm[256];
    const int tid = threadIdx.x;
    float v = 0.0f;
    for (int i = tid; i < BATCH; i += 256) v += g_part[i];  // fixed order: deterministic
    sm[tid] = v;
    __syncthreads();
#pragma unroll
    for (int s = 128; s; s >>= 1) {
        if (tid < s) sm[tid] += sm[tid + s];
        __syncthreads();
    }
    if (tid == 0) out[0] = sm[0] * (1.0f / BATCH);
}

extern "C" void kernel_launch(void* const* d_in, const int* in_sizes, int n_in,
                              void* d_out, int out_size)
{
    const float* emissions = (const float*)d_in[0];
    const int*   tags      = (const int*)d_in[1];
    const int*   mask      = (const int*)d_in[2];
    const float* trans     = (const float*)d_in[3];

    crf_fwd_kernel<<<BATCH / WARPS_PER_BLOCK, THREADS>>>(emissions, tags, mask, trans);
    crf_reduce_kernel<<<1, 256>>>((float*)d_out);
}

// round 2
// speedup vs baseline: 1.1538x; 1.1538x over previous
#include <cuda_runtime.h>
#include <cstdint>

#define NTAGS 24
#define SEQ   512
#define BATCH 2048
#define WARPS_PER_BLOCK 4
#define THREADS (WARPS_PER_BLOCK * 32)
#define NCHUNK (SEQ / 8)   // 64 chunks of 8 timesteps

__device__ float    g_part[BATCH];
__device__ unsigned g_ctr = 0;

__global__ void __launch_bounds__(THREADS) crf_fwd_kernel(
    const float* __restrict__ emissions,   // [BATCH, SEQ, NTAGS]
    const int*   __restrict__ tags,        // [BATCH, SEQ]
    const int*   __restrict__ mask,        // [BATCH, SEQ]
    const float* __restrict__ trans,       // [NTAGS, NTAGS]
    float*       __restrict__ out)
{
    __shared__ float s_traw[NTAGS * NTAGS];
    __shared__ __align__(16) float s_p[WARPS_PER_BLOCK][2][32];
    __shared__ int s_done;
    __shared__ float s_red[THREADS];

    const int tid  = threadIdx.x;
    const int lane = tid & 31;
    const int wid  = tid >> 5;
    const int b    = blockIdx.x * WARPS_PER_BLOCK + wid;

    for (int i = tid; i < NTAGS * NTAGS; i += THREADS) s_traw[i] = trans[i];
    __syncthreads();

    const bool act = (lane < NTAGS);

    // tcol[i] = exp(trans[i][lane]) — lane owns column `lane` of expT.
    float tcol[NTAGS];
#pragma unroll
    for (int i = 0; i < NTAGS; i++)
        tcol[i] = act ? __expf(trans[i * NTAGS + lane]) : 0.0f;

    const float* em = emissions + (size_t)b * (SEQ * NTAGS);
    const int*   tg = tags + (size_t)b * SEQ;
    const int*   mk = mask + (size_t)b * SEQ;

    // Double-buffered prefetch state (8 steps per chunk).
    float ebuf[2][8];
    int4  tgb[2][2];
    int4  mkb[2][2];

#define PREFETCH(CHUNK, BUF)                                                  \
    do {                                                                      \
        const int _t0 = (CHUNK) * 8;                                          \
        _Pragma("unroll")                                                     \
        for (int _k = 0; _k < 8; _k++)                                        \
            ebuf[BUF][_k] = act ? em[(_t0 + _k) * NTAGS + lane] : -1e30f;     \
        tgb[BUF][0] = *(const int4*)(tg + _t0);                               \
        tgb[BUF][1] = *(const int4*)(tg + _t0 + 4);                           \
        mkb[BUF][0] = *(const int4*)(mk + _t0);                               \
        mkb[BUF][1] = *(const int4*)(mk + _t0 + 4);                           \
    } while (0)

    PREFETCH(0, 0);
    PREFETCH(1, 1);

    // ---- t = 0 init: alpha0 = emissions[:,0] ----
    const float e0 = ebuf[0][0];
    float m0 = e0;
#pragma unroll
    for (int o = 16; o; o >>= 1)
        m0 = fmaxf(m0, __shfl_xor_sync(0xffffffffu, m0, o));
    float p = act ? __expf(e0 - m0) : 0.0f;  // p[j] = exp(alpha[j] - C)
    float C = m0;

    const int tag0 = tgb[0][0].x;
    const int mk0  = mkb[0][0].x;
    float gold = mk0 ? __shfl_sync(0xffffffffu, e0, tag0) : 0.0f;
    int   prev_tag = tag0;

    float* pw = &s_p[wid][0][0];
    int parity = 0;

    // One recursion step. k is compile-time within the unrolled chunk body.
#define STEP(E, TAG, MT, DO_RESCALE)                                          \
    do {                                                                      \
        float* _buf = pw + (parity << 5);                                     \
        parity ^= 1;                                                          \
        _buf[lane] = p;                                                       \
        __syncwarp();                                                         \
        const float4* _b4 = (const float4*)_buf;                              \
        const float4 P0 = _b4[0], P1 = _b4[1], P2 = _b4[2],                   \
                     P3 = _b4[3], P4 = _b4[4], P5 = _b4[5];                   \
        float s0 = P0.x * tcol[0];                                            \
        float s1 = P0.y * tcol[1];                                            \
        float s2 = P0.z * tcol[2];                                            \
        float s3 = P0.w * tcol[3];                                            \
        s0 = fmaf(P1.x, tcol[4],  s0);                                        \
        s1 = fmaf(P1.y, tcol[5],  s1);                                        \
        s2 = fmaf(P1.z, tcol[6],  s2);                                        \
        s3 = fmaf(P1.w, tcol[7],  s3);                                        \
        s0 = fmaf(P2.x, tcol[8],  s0);                                        \
        s1 = fmaf(P2.y, tcol[9],  s1);                                        \
        s2 = fmaf(P2.z, tcol[10], s2);                                        \
        s3 = fmaf(P2.w, tcol[11], s3);                                        \
        s0 = fmaf(P3.x, tcol[12], s0);                                        \
        s1 = fmaf(P3.y, tcol[13], s1);                                        \
        s2 = fmaf(P3.z, tcol[14], s2);                                        \
        s3 = fmaf(P3.w, tcol[15], s3);                                        \
        s0 = fmaf(P4.x, tcol[16], s0);                                        \
        s1 = fmaf(P4.y, tcol[17], s1);                                        \
        s2 = fmaf(P4.z, tcol[18], s2);                                        \
        s3 = fmaf(P4.w, tcol[19], s3);                                        \
        s0 = fmaf(P5.x, tcol[20], s0);                                        \
        s1 = fmaf(P5.y, tcol[21], s1);                                        \
        s2 = fmaf(P5.z, tcol[22], s2);                                        \
        s3 = fmaf(P5.w, tcol[23], s3);                                        \
        const float _s = (s0 + s1) + (s2 + s3);                               \
        const float _u = _s * __expf(E);                                      \
        p = (MT) ? _u : p;                                                    \
        const float _ee = __shfl_sync(0xffffffffu, (E), (TAG));               \
        if (MT) gold += _ee + s_traw[prev_tag * NTAGS + (TAG)];               \
        prev_tag = (TAG);                                                     \
        if (DO_RESCALE) {                                                     \
            float _m = p;                                                     \
            _Pragma("unroll")                                                 \
            for (int _o = 16; _o; _o >>= 1)                                   \
                _m = fmaxf(_m, __shfl_xor_sync(0xffffffffu, _m, _o));         \
            p *= (1.0f / _m);                                                 \
            C += __logf(_m);                                                  \
        }                                                                     \
    } while (0)

#define TGK(BUF, K) (((K) < 4) ? (&tgb[BUF][0].x)[K] : (&tgb[BUF][1].x)[(K)-4])
#define MKK(BUF, K) (((K) < 4) ? (&mkb[BUF][0].x)[K] : (&mkb[BUF][1].x)[(K)-4])

    // ---- chunk 0: steps k = 1..7 (k = 0 consumed by init) ----
    {
        const int B = 0;
#pragma unroll
        for (int k = 1; k < 8; k++)
            STEP(ebuf[B][k], TGK(B, k), MKK(B, k), (k == 3 || k == 7));
    }

    // ---- chunks 1..63 ----
    for (int c = 1; c < NCHUNK; c++) {
        const int B = c & 1;
        if (c + 1 < NCHUNK) {
            if ((c + 1) & 1) { PREFETCH(c + 1, 1); }
            else             { PREFETCH(c + 1, 0); }
        }
#pragma unroll
        for (int k = 0; k < 8; k++)
            STEP(ebuf[B][k], TGK(B, k), MKK(B, k), (k == 3 || k == 7));
    }

    // log_den = C + log(sum_j p[j])
    float m = p;
#pragma unroll
    for (int o = 16; o; o >>= 1)
        m = fmaxf(m, __shfl_xor_sync(0xffffffffu, m, o));
    float zs = p * (1.0f / m);
#pragma unroll
    for (int o = 16; o; o >>= 1)
        zs += __shfl_xor_sync(0xffffffffu, zs, o);
    const float log_den = C + __logf(m) + __logf(zs);

    if (lane == 0) g_part[b] = log_den - gold;

    // ---- fused deterministic reduction: last block sums in fixed order ----
    __syncthreads();
    if (tid == 0) {
        __threadfence();
        unsigned prev = atomicInc(&g_ctr, gridDim.x - 1);  // wraps to 0 when last
        s_done = (prev == gridDim.x - 1);
    }
    __syncthreads();
    if (s_done) {
        float v = 0.0f;
        for (int i = tid; i < BATCH; i += THREADS) v += g_part[i];  // fixed order
        s_red[tid] = v;
        __syncthreads();
#pragma unroll
        for (int s = THREADS / 2; s; s >>= 1) {
            if (tid < s) s_red[tid] += s_red[tid + s];
            __syncthreads();
        }
        if (tid == 0) out[0] = s_red[0] * (1.0f / BATCH);
    }
}

extern "C" void kernel_launch(void* const* d_in, const int* in_sizes, int n_in,
                              void* d_out, int out_size)
{
    const float* emissions = (const float*)d_in[0];
    const int*   tags      = (const int*)d_in[1];
    const int*   mask      = (const int*)d_in[2];
    const float* trans     = (const float*)d_in[3];

    crf_fwd_kernel<<<BATCH / WARPS_PER_BLOCK, THREADS>>>(
        emissions, tags, mask, trans, (float*)d_out);
}

// round 3
// speedup vs baseline: 1.1545x; 1.0006x over previous
#include <cuda_runtime.h>
#include <cstdint>

#define NTAGS 24
#define SEQ   512
#define BATCH 2048
#define WARPS_PER_BLOCK 4
#define THREADS (WARPS_PER_BLOCK * 32)
#define NCHUNK (SEQ / 8)   // 64 chunks of 8 timesteps

__device__ float    g_part[BATCH];
__device__ unsigned g_ctr = 0;

__global__ void __launch_bounds__(THREADS) crf_fwd_kernel(
    const float* __restrict__ emissions,   // [BATCH, SEQ, NTAGS]
    const int*   __restrict__ tags,        // [BATCH, SEQ]
    const int*   __restrict__ mask,        // [BATCH, SEQ]
    const float* __restrict__ trans,       // [NTAGS, NTAGS]
    float*       __restrict__ out)
{
    __shared__ float s_traw[NTAGS * NTAGS];
    __shared__ __align__(16) float s_p[WARPS_PER_BLOCK][2][32];
    __shared__ int s_done;
    __shared__ float s_red[THREADS];

    const int tid  = threadIdx.x;
    const int lane = tid & 31;
    const int wid  = tid >> 5;
    const int b    = blockIdx.x * WARPS_PER_BLOCK + wid;

    for (int i = tid; i < NTAGS * NTAGS; i += THREADS) s_traw[i] = trans[i];
    __syncthreads();

    const bool act = (lane < NTAGS);

    // tcol[i] = exp(trans[i][lane]) — lane owns column `lane` of expT.
    float tcol[NTAGS];
#pragma unroll
    for (int i = 0; i < NTAGS; i++)
        tcol[i] = act ? __expf(trans[i * NTAGS + lane]) : 0.0f;

    const float* em = emissions + (size_t)b * (SEQ * NTAGS);
    const int*   tg = tags + (size_t)b * SEQ;
    const int*   mk = mask + (size_t)b * SEQ;

    // Double-buffered prefetch state (8 steps per chunk).
    float ebuf[2][8];
    int4  tgb[2][2];
    int4  mkb[2][2];

#define PREFETCH(CHUNK, BUF)                                                  \
    do {                                                                      \
        const int _t0 = (CHUNK) * 8;                                          \
        _Pragma("unroll")                                                     \
        for (int _k = 0; _k < 8; _k++)                                        \
            ebuf[BUF][_k] = act ? em[(_t0 + _k) * NTAGS + lane] : -1e30f;     \
        tgb[BUF][0] = *(const int4*)(tg + _t0);                               \
        tgb[BUF][1] = *(const int4*)(tg + _t0 + 4);                           \
        mkb[BUF][0] = *(const int4*)(mk + _t0);                               \
        mkb[BUF][1] = *(const int4*)(mk + _t0 + 4);                           \
    } while (0)

    PREFETCH(0, 0);
    PREFETCH(1, 1);

    // ---- t = 0 init: alpha0 = emissions[:,0] ----
    const float e0 = ebuf[0][0];
    float m0 = e0;
#pragma unroll
    for (int o = 16; o; o >>= 1)
        m0 = fmaxf(m0, __shfl_xor_sync(0xffffffffu, m0, o));
    float p = act ? __expf(e0 - m0) : 0.0f;  // p[j] = exp(alpha[j] - C)
    float C = m0;

    const int tag0 = tgb[0][0].x;
    const int mk0  = mkb[0][0].x;
    float gold = mk0 ? __shfl_sync(0xffffffffu, e0, tag0) : 0.0f;
    int   prev_tag = tag0;

    float* pw = &s_p[wid][0][0];
    int parity = 0;

    // One recursion step. k is compile-time within the unrolled chunk body.
#define STEP(E, TAG, MT, DO_RESCALE)                                          \
    do {                                                                      \
        float* _buf = pw + (parity << 5);                                     \
        parity ^= 1;                                                          \
        _buf[lane] = p;                                                       \
        __syncwarp();                                                         \
        const float4* _b4 = (const float4*)_buf;                              \
        const float4 P0 = _b4[0], P1 = _b4[1], P2 = _b4[2],                   \
                     P3 = _b4[3], P4 = _b4[4], P5 = _b4[5];                   \
        float s0 = P0.x * tcol[0];                                            \
        float s1 = P0.y * tcol[1];                                            \
        float s2 = P0.z * tcol[2];                                            \
        float s3 = P0.w * tcol[3];                                            \
        s0 = fmaf(P1.x, tcol[4],  s0);                                        \
        s1 = fmaf(P1.y, tcol[5],  s1);                                        \
        s2 = fmaf(P1.z, tcol[6],  s2);                                        \
        s3 = fmaf(P1.w, tcol[7],  s3);                                        \
        s0 = fmaf(P2.x, tcol[8],  s0);                                        \
        s1 = fmaf(P2.y, tcol[9],  s1);                                        \
        s2 = fmaf(P2.z, tcol[10], s2);                                        \
        s3 = fmaf(P2.w, tcol[11], s3);                                        \
        s0 = fmaf(P3.x, tcol[12], s0);                                        \
        s1 = fmaf(P3.y, tcol[13], s1);                                        \
        s2 = fmaf(P3.z, tcol[14], s2);                                        \
        s3 = fmaf(P3.w, tcol[15], s3);                                        \
        s0 = fmaf(P4.x, tcol[16], s0);                                        \
        s1 = fmaf(P4.y, tcol[17], s1);                                        \
        s2 = fmaf(P4.z, tcol[18], s2);                                        \
        s3 = fmaf(P4.w, tcol[19], s3);                                        \
        s0 = fmaf(P5.x, tcol[20], s0);                                        \
        s1 = fmaf(P5.y, tcol[21], s1);                                        \
        s2 = fmaf(P5.z, tcol[22], s2);                                        \
        s3 = fmaf(P5.w, tcol[23], s3);                                        \
        const float _s = (s0 + s1) + (s2 + s3);                               \
        const float _u = _s * __expf(E);                                      \
        p = (MT) ? _u : p;                                                    \
        const float _ee = __shfl_sync(0xffffffffu, (E), (TAG));               \
        if (MT) gold += _ee + s_traw[prev_tag * NTAGS + (TAG)];               \
        prev_tag = (TAG);                                                     \
        if (DO_RESCALE) {                                                     \
            float _m = p;                                                     \
            _Pragma("unroll")                                                 \
            for (int _o = 16; _o; _o >>= 1)                                   \
                _m = fmaxf(_m, __shfl_xor_sync(0xffffffffu, _m, _o));         \
            p *= (1.0f / _m);                                                 \
            C += __logf(_m);                                                  \
        }                                                                     \
    } while (0)

#define TGK(BUF, K) (((K) < 4) ? (&tgb[BUF][0].x)[K] : (&tgb[BUF][1].x)[(K)-4])
#define MKK(BUF, K) (((K) < 4) ? (&mkb[BUF][0].x)[K] : (&mkb[BUF][1].x)[(K)-4])

    // ---- chunk 0: steps k = 1..7 (k = 0 consumed by init) ----
    {
        const int B = 0;
#pragma unroll
        for (int k = 1; k < 8; k++)
            STEP(ebuf[B][k], TGK(B, k), MKK(B, k), (k == 3 || k == 7));
    }

    // ---- chunks 1..63 ----
    for (int c = 1; c < NCHUNK; c++) {
        const int B = c & 1;
        if (c + 1 < NCHUNK) {
            if ((c + 1) & 1) { PREFETCH(c + 1, 1); }
            else             { PREFETCH(c + 1, 0); }
        }
#pragma unroll
        for (int k = 0; k < 8; k++)
            STEP(ebuf[B][k], TGK(B, k), MKK(B, k), (k == 3 || k == 7));
    }

    // log_den = C + log(sum_j p[j])
    float m = p;
#pragma unroll
    for (int o = 16; o; o >>= 1)
        m = fmaxf(m, __shfl_xor_sync(0xffffffffu, m, o));
    float zs = p * (1.0f / m);
#pragma unroll
    for (int o = 16; o; o >>= 1)
        zs += __shfl_xor_sync(0xffffffffu, zs, o);
    const float log_den = C + __logf(m) + __logf(zs);

    if (lane == 0) g_part[b] = log_den - gold;

    // ---- fused deterministic reduction: last block sums in fixed order ----
    __syncthreads();
    if (tid == 0) {
        __threadfence();
        unsigned prev = atomicInc(&g_ctr, gridDim.x - 1);  // wraps to 0 when last
        s_done = (prev == gridDim.x - 1);
    }
    __syncthreads();
    if (s_done) {
        float v = 0.0f;
        for (int i = tid; i < BATCH; i += THREADS) v += g_part[i];  // fixed order
        s_red[tid] = v;
        __syncthreads();
#pragma unroll
        for (int s = THREADS / 2; s; s >>= 1) {
            if (tid < s) s_red[tid] += s_red[tid + s];
            __syncthreads();
        }
        if (tid == 0) out[0] = s_red[0] * (1.0f / BATCH);
    }
}

extern "C" void kernel_launch(void* const* d_in, const int* in_sizes, int n_in,
                              void* d_out, int out_size)
{
    const float* emissions = (const float*)d_in[0];
    const int*   tags      = (const int*)d_in[1];
    const int*   mask      = (const int*)d_in[2];
    const float* trans     = (const float*)d_in[3];

    crf_fwd_kernel<<<BATCH / WARPS_PER_BLOCK, THREADS>>>(
        emissions, tags, mask, trans, (float*)d_out);
}

// round 4
// speedup vs baseline: 2.2548x; 1.9530x over previous
#include <cuda_runtime.h>
#include <cstdint>

#define NTAGS 24
#define SEQ   512
#define BATCH 2048
#define WPB   4
#define THREADS (WPB * 32)
#define CH    8
#define NCHUNK (SEQ / CH)
#define FULL  0xffffffffu

typedef unsigned long long u64;

__device__ float    g_part[BATCH];
__device__ unsigned g_ctr = 0;

static __device__ __forceinline__ u64 pk2(float lo, float hi) {
    u64 r; asm("mov.b64 %0, {%1, %2};" : "=l"(r) : "f"(lo), "f"(hi)); return r;
}
static __device__ __forceinline__ void un2(u64 v, float& lo, float& hi) {
    asm("mov.b64 {%0, %1}, %2;" : "=f"(lo), "=f"(hi) : "l"(v));
}
static __device__ __forceinline__ u64 fma2(u64 a, u64 b, u64 c) {
    u64 d; asm("fma.rn.f32x2 %0, %1, %2, %3;" : "=l"(d) : "l"(a), "l"(b), "l"(c)); return d;
}
static __device__ __forceinline__ u64 mul2(u64 a, u64 b) {
    u64 d; asm("mul.rn.f32x2 %0, %1, %2;" : "=l"(d) : "l"(a), "l"(b)); return d;
}
static __device__ __forceinline__ u64 add2(u64 a, u64 b) {
    u64 d; asm("add.rn.f32x2 %0, %1, %2;" : "=l"(d) : "l"(a), "l"(b)); return d;
}

__global__ void __launch_bounds__(THREADS) crf_fwd_kernel(
    const float* __restrict__ emissions,
    const int*   __restrict__ tags,
    const int*   __restrict__ mask,
    const float* __restrict__ trans,
    float*       __restrict__ out)
{
    __shared__ float s_traw[NTAGS * NTAGS];
    __shared__ __align__(16) float s_p[WPB][2][32];
    __shared__ int s_done;
    __shared__ float s_red[THREADS];

    const int tid  = threadIdx.x;
    const int lane = tid & 31;
    const int wid  = tid >> 5;
    const int b    = blockIdx.x * WPB + wid;

    for (int i = tid; i < NTAGS * NTAGS; i += THREADS) s_traw[i] = trans[i];
    __syncthreads();

    const bool act = (lane < NTAGS);
    const bool isg = (lane >= NTAGS);       // gold-score lanes 24..31
    const int  gk  = lane - NTAGS;          // timestep-in-chunk owned by gold lane

    // tc[k] = pk( exp(T[2k][lane]), exp(T[2k+1][lane]) )
    u64 tc[12];
#pragma unroll
    for (int k = 0; k < 12; k++) {
        float a = act ? __expf(trans[(2 * k)     * NTAGS + lane]) : 0.f;
        float c = act ? __expf(trans[(2 * k + 1) * NTAGS + lane]) : 0.f;
        tc[k] = pk2(a, c);
    }

    const float* em = emissions + (size_t)b * (SEQ * NTAGS);
    const int*   tg = tags + (size_t)b * SEQ;
    const int*   mk = mask + (size_t)b * SEQ;

    float eb[2][CH];   // raw emissions, double-buffered
    int   mb[2][CH];   // masks

#define PRE(C, B)                                                             \
    do {                                                                      \
        const int _t0 = (C) * CH;                                             \
        _Pragma("unroll")                                                     \
        for (int _k = 0; _k < CH; _k++)                                       \
            eb[B][_k] = act ? em[(_t0 + _k) * NTAGS + lane] : -1e30f;         \
        int4 _ma = *(const int4*)(mk + _t0);                                  \
        int4 _mc = *(const int4*)(mk + _t0 + 4);                              \
        mb[B][0] = _ma.x; mb[B][1] = _ma.y; mb[B][2] = _ma.z; mb[B][3] = _ma.w;\
        mb[B][4] = _mc.x; mb[B][5] = _mc.y; mb[B][6] = _mc.z; mb[B][7] = _mc.w;\
    } while (0)

    PRE(0, 0);
    PRE(1, 1);

    // Gold-lane state: tags/masks for current chunk, loaded one chunk ahead.
    int   tt = isg ? tg[gk] : 0;
    int   gm = isg ? mk[gk] : 0;
    int   tcarry = 0;
    float gold = 0.f, ge = 0.f;

    // ---- init t = 0: alpha0 = emissions[:,0] ----
    const float e0 = eb[0][0];
    float m0 = e0;
#pragma unroll
    for (int o = 16; o; o >>= 1)
        m0 = fmaxf(m0, __shfl_xor_sync(FULL, m0, o));
    float p  = act ? __expf(e0 - m0) : 0.f;
    float Cc = m0;

    float* pw = &s_p[wid][0][0];
    int parity = 0;

#define STEP(EX, MT, RS)                                                      \
    do {                                                                      \
        float* _b = pw + (parity << 5);                                       \
        parity ^= 1;                                                          \
        _b[lane] = p;                                                         \
        __syncwarp();                                                         \
        const ulonglong2* _q = (const ulonglong2*)_b;                         \
        ulonglong2 q0 = _q[0], q1 = _q[1], q2 = _q[2];                        \
        u64 a0 = mul2(q0.x, tc[0]);                                           \
        u64 a1 = mul2(q0.y, tc[1]);                                           \
        u64 a2 = mul2(q1.x, tc[2]);                                           \
        u64 a3 = mul2(q1.y, tc[3]);                                           \
        a0 = fma2(q2.x, tc[4], a0);                                           \
        a1 = fma2(q2.y, tc[5], a1);                                           \
        ulonglong2 q3 = _q[3], q4 = _q[4], q5 = _q[5];                        \
        a2 = fma2(q3.x, tc[6], a2);                                           \
        a3 = fma2(q3.y, tc[7], a3);                                           \
        a0 = fma2(q4.x, tc[8], a0);                                           \
        a1 = fma2(q4.y, tc[9], a1);                                           \
        a2 = fma2(q5.x, tc[10], a2);                                          \
        a3 = fma2(q5.y, tc[11], a3);                                          \
        u64 _aa = add2(add2(a0, a1), add2(a2, a3));                           \
        float _sl, _sh; un2(_aa, _sl, _sh);                                   \
        const float _u = (_sl + _sh) * (EX);                                  \
        p = (MT) ? _u : p;                                                    \
        if (RS) {                                                             \
            float _m = p;                                                     \
            _Pragma("unroll")                                                 \
            for (int _o = 16; _o; _o >>= 1)                                   \
                _m = fmaxf(_m, __shfl_xor_sync(FULL, _m, _o));                \
            p *= (1.0f / _m);                                                 \
            Cc += __logf(_m);                                                 \
        }                                                                     \
    } while (0)

    // Chunk body. BB = compile-time buffer index, K0 = first step in chunk.
#define CBODY(BB, K0)                                                         \
    do {                                                                      \
        float expe[CH]; int ml[CH];                                           \
        _Pragma("unroll")                                                     \
        for (int k = 0; k < CH; k++) {                                        \
            expe[k] = __expf(eb[BB][k]);                                      \
            ml[k]   = mb[BB][k];                                              \
        }                                                                     \
        if (isg) ge = em[(c * CH + gk) * NTAGS + tt];   /* gather, used late */\
        int tt_nx = tt, gm_nx = gm;                                           \
        if (c + 1 < NCHUNK) {                                                 \
            const int _tn = (c + 1) * CH + gk;                                \
            tt_nx = isg ? tg[_tn] : 0;                                        \
            gm_nx = isg ? mk[_tn] : 0;                                        \
        }                                                                     \
        if (c + 2 < NCHUNK) PRE(c + 2, BB);                                   \
        _Pragma("unroll")                                                     \
        for (int k = K0; k < CH; k++)                                         \
            STEP(expe[k], ml[k], (k == 3 || k == 7));                         \
        int _tp = __shfl_up_sync(FULL, tt, 1);                                \
        if (gk == 0) _tp = tcarry;                                            \
        if (isg && gm) {                                                      \
            float _gt = (c == 0 && gk == 0) ? 0.f                             \
                                            : s_traw[_tp * NTAGS + tt];       \
            gold += ge + _gt;                                                 \
        }                                                                     \
        tcarry = __shfl_sync(FULL, tt, 31);                                   \
        tt = tt_nx; gm = gm_nx;                                               \
    } while (0)

    { const int c = 0; CBODY(0, 1); }          // k = 0 consumed by init
    for (int c = 1; c < NCHUNK; c++) {
        if (c & 1) CBODY(1, 0);
        else       CBODY(0, 0);
    }

    // ---- log_den = C + log(sum_j p[j]) ----
    float m = p;
#pragma unroll
    for (int o = 16; o; o >>= 1)
        m = fmaxf(m, __shfl_xor_sync(FULL, m, o));
    float zs = p * (1.0f / m);
#pragma unroll
    for (int o = 16; o; o >>= 1)
        zs += __shfl_xor_sync(FULL, zs, o);
    const float log_den = Cc + __logf(m) + __logf(zs);

    // ---- gold: reduce over lanes 24..31 (aligned group: xor 1,2,4) ----
    gold += __shfl_xor_sync(FULL, gold, 1);
    gold += __shfl_xor_sync(FULL, gold, 2);
    gold += __shfl_xor_sync(FULL, gold, 4);
    const float gold_all = __shfl_sync(FULL, gold, NTAGS);

    if (lane == 0) g_part[b] = log_den - gold_all;

    // ---- fused deterministic reduction: last block sums in fixed order ----
    __syncthreads();
    if (tid == 0) {
        __threadfence();
        unsigned prev = atomicInc(&g_ctr, gridDim.x - 1);
        s_done = (prev == gridDim.x - 1);
    }
    __syncthreads();
    if (s_done) {
        float v = 0.0f;
        for (int i = tid; i < BATCH; i += THREADS) v += g_part[i];
        s_red[tid] = v;
        __syncthreads();
#pragma unroll
        for (int s = THREADS / 2; s; s >>= 1) {
            if (tid < s) s_red[tid] += s_red[tid + s];
            __syncthreads();
        }
        if (tid == 0) out[0] = s_red[0] * (1.0f / BATCH);
    }
}

extern "C" void kernel_launch(void* const* d_in, const int* in_sizes, int n_in,
                              void* d_out, int out_size)
{
    const float* emissions = (const float*)d_in[0];
    const int*   tags      = (const int*)d_in[1];
    const int*   mask      = (const int*)d_in[2];
    const float* trans     = (const float*)d_in[3];

    crf_fwd_kernel<<<BATCH / WPB, THREADS>>>(
        emissions, tags, mask, trans, (float*)d_out);
}